// round 2
// baseline (speedup 1.0000x reference)
#include <cuda_runtime.h>
#include <cuda_bf16.h>
#include <stdint.h>

#define S_REAL   308
#define SP       320     // padded state count
#define E_DIM    126
#define T_LEN    4096
#define NBATCH   32
#define NIP      160     // SP/2 (i-pairs)
#define JGROUPS  80
#define HSPLIT   8
#define SCAN_THREADS 640

// Scratch (device globals — no allocation in kernel_launch)
__device__ __nv_bfloat16 g_emis[(size_t)NBATCH * T_LEN * SP];   // 80 MB
__device__ uint32_t      g_apk[NIP * SP];                        // packed A, 200 KB

__device__ __forceinline__ __nv_bfloat162 u32_bf2(uint32_t v) {
    return *reinterpret_cast<__nv_bfloat162*>(&v);
}
__device__ __forceinline__ uint32_t bf2_u32(__nv_bfloat162 v) {
    return *reinterpret_cast<uint32_t*>(&v);
}

// ---------------------------------------------------------------------------
// Pack A (fp32 [308][308]) into bf16x2 words.
// Word for (ip, j): lo = A[2ip][j], hi = A[2ip+1][j], zero-padded to 320x320.
// Stored at g_apk[(ip*80 + jg)*4 + q] where j = jg + 80*q, so one LDG.128 per
// thread fetches its 4 strided-j words and a warp (consecutive jg) reads a
// contiguous 512B block.
// ---------------------------------------------------------------------------
__global__ void prep_apk_kernel(const float* __restrict__ A) {
    int idx = blockIdx.x * blockDim.x + threadIdx.x;
    if (idx >= NIP * SP) return;
    int ip = idx / SP;
    int j  = idx - ip * SP;
    int i0 = 2 * ip, i1 = i0 + 1;
    float a0 = (i0 < S_REAL && j < S_REAL) ? A[i0 * S_REAL + j] : 0.f;
    float a1 = (i1 < S_REAL && j < S_REAL) ? A[i1 * S_REAL + j] : 0.f;
    __nv_bfloat162 w = __floats2bfloat162_rn(a0, a1);  // lo = a0, hi = a1
    int jg = j % JGROUPS, q = j / JGROUPS;
    g_apk[(ip * JGROUPS + jg) * 4 + q] = bf2_u32(w);
}

// ---------------------------------------------------------------------------
// Emission GEMM: emis[m][n] = sum_e inputs[m][e] * B[n][e]   (m = b*T+t)
// M=131072, N=320 (308 real, rest 0), K=126 (padded to 128).
// 64x64 tiles, 256 threads, 4x4 microtile, fp32 accum, bf16 store.
// ---------------------------------------------------------------------------
__global__ void __launch_bounds__(256)
emis_gemm_kernel(const float* __restrict__ inp, const float* __restrict__ Bm) {
    __shared__ float sA[64][32];   // [m][k]
    __shared__ float sB[32][64];   // [k][n]

    const int tid = threadIdx.x;
    const int tx = tid & 15;       // 0..15 -> n microtile
    const int ty = tid >> 4;       // 0..15 -> m microtile
    const int n0 = blockIdx.x * 64;
    const int m0 = blockIdx.y * 64;

    float acc[4][4];
#pragma unroll
    for (int u = 0; u < 4; ++u)
#pragma unroll
        for (int v = 0; v < 4; ++v) acc[u][v] = 0.f;

    for (int k0 = 0; k0 < 128; k0 += 32) {
        // load inputs tile: 64x32 = 2048 floats, 8 per thread, coalesced in k
#pragma unroll
        for (int r = 0; r < 8; ++r) {
            int lin = tid + r * 256;
            int mm = lin >> 5, kk = lin & 31;
            int k = k0 + kk;
            sA[mm][kk] = (k < E_DIM) ? inp[(size_t)(m0 + mm) * E_DIM + k] : 0.f;
        }
        // load B^T tile: sB[kk][n] = B[n0+n][k0+kk]
#pragma unroll
        for (int r = 0; r < 8; ++r) {
            int lin = tid + r * 256;
            int kk = lin >> 6, n = lin & 63;
            int k = k0 + kk;
            int nn = n0 + n;
            sB[kk][n] = (k < E_DIM && nn < S_REAL) ? Bm[(size_t)nn * E_DIM + k] : 0.f;
        }
        __syncthreads();
#pragma unroll
        for (int kk = 0; kk < 32; ++kk) {
            float4 bv = *reinterpret_cast<const float4*>(&sB[kk][tx * 4]);
            float av0 = sA[ty * 4 + 0][kk];
            float av1 = sA[ty * 4 + 1][kk];
            float av2 = sA[ty * 4 + 2][kk];
            float av3 = sA[ty * 4 + 3][kk];
            acc[0][0] += av0 * bv.x; acc[0][1] += av0 * bv.y;
            acc[0][2] += av0 * bv.z; acc[0][3] += av0 * bv.w;
            acc[1][0] += av1 * bv.x; acc[1][1] += av1 * bv.y;
            acc[1][2] += av1 * bv.z; acc[1][3] += av1 * bv.w;
            acc[2][0] += av2 * bv.x; acc[2][1] += av2 * bv.y;
            acc[2][2] += av2 * bv.z; acc[2][3] += av2 * bv.w;
            acc[3][0] += av3 * bv.x; acc[3][1] += av3 * bv.y;
            acc[3][2] += av3 * bv.z; acc[3][3] += av3 * bv.w;
        }
        __syncthreads();
    }
    // store bf16 (pairs)
#pragma unroll
    for (int u = 0; u < 4; ++u) {
        int m = m0 + ty * 4 + u;
        size_t base = (size_t)m * SP + n0 + tx * 4;
#pragma unroll
        for (int v = 0; v < 4; v += 2) {
            __nv_bfloat162 p = __floats2bfloat162_rn(acc[u][v], acc[u][v + 1]);
            *reinterpret_cast<uint32_t*>(&g_emis[base + v]) = bf2_u32(p);
        }
    }
}

// ---------------------------------------------------------------------------
// Scan kernel: one CTA per batch. 640 threads = 8 i-splits x 80 j-groups.
// Thread (h, jg) accumulates A[i, j] * alpha[i] over i in [h*40, h*40+40)
// for its 4 strided outputs j = jg + {0,80,160,240}, using HFMA2 on bf16x2
// (i-pairs), collapsing to fp32 every 10 pairs (20 terms).
// Cross-h reduction via smem; alpha kept unnormalized in bf16, renormalized
// (with log-accumulation) every 8 steps — telescopes to sum of log z_t.
// ---------------------------------------------------------------------------
__global__ void __launch_bounds__(SCAN_THREADS, 1)
scan_kernel(const float* __restrict__ Ivec, float* __restrict__ out) {
    __shared__ uint32_t s_alpha32[NIP];        // bf16 alpha[320] as pairs
    __shared__ float    s_red[HSPLIT][SP];
    __shared__ float    s_outf[SP];
    __shared__ float    s_inv;

    const int b   = blockIdx.x;
    const int tid = threadIdx.x;
    const int h   = tid / JGROUPS;             // 0..7
    const int jg  = tid - h * JGROUPS;         // 0..79
    const bool is_red = (tid < SP);
    const int j = tid;

    const __nv_bfloat16* erow = g_emis + (size_t)b * T_LEN * SP;
    // base for this thread's A slice: uint4 index (ip*80 + jg), ip = h*20 + kk
    const uint4* Ap = reinterpret_cast<const uint4*>(g_apk) + (h * 20) * JGROUPS + jg;

    float ll = 0.f;

    // t = 0: alpha0 = I * e0 (unnormalized)
    if (is_red) {
        float e0 = __bfloat162float(erow[j]);
        float w  = (j < S_REAL) ? Ivec[j] : 0.f;
        reinterpret_cast<__nv_bfloat16*>(s_alpha32)[j] = __float2bfloat16(w * e0);
    }
    __syncthreads();

    for (int t = 1; t < T_LEN; ++t) {
        // prefetch emission for this step (used ~800 cycles later)
        float e = 0.f;
        if (is_red) e = __bfloat162float(erow[(size_t)t * SP + j]);

        // load this h-slice's 20 alpha pair-words (warp-broadcast LDS.128)
        uint4 av[5];
        const uint4* al4 = reinterpret_cast<const uint4*>(s_alpha32);
#pragma unroll
        for (int r = 0; r < 5; ++r) av[r] = al4[h * 5 + r];
        const uint32_t* aw = reinterpret_cast<const uint32_t*>(av);

        float f0 = 0.f, f1 = 0.f, f2 = 0.f, f3 = 0.f;
#pragma unroll
        for (int c = 0; c < 2; ++c) {
            __nv_bfloat162 a0 = u32_bf2(0u), a1 = u32_bf2(0u);
            __nv_bfloat162 a2 = u32_bf2(0u), a3 = u32_bf2(0u);
#pragma unroll
            for (int k = 0; k < 10; ++k) {
                const int kk = c * 10 + k;
                uint4 w = Ap[kk * JGROUPS];
                __nv_bfloat162 al = u32_bf2(aw[kk]);
                a0 = __hfma2(u32_bf2(w.x), al, a0);
                a1 = __hfma2(u32_bf2(w.y), al, a1);
                a2 = __hfma2(u32_bf2(w.z), al, a2);
                a3 = __hfma2(u32_bf2(w.w), al, a3);
            }
            float2 p;
            p = __bfloat1622float2(a0); f0 += p.x + p.y;
            p = __bfloat1622float2(a1); f1 += p.x + p.y;
            p = __bfloat1622float2(a2); f2 += p.x + p.y;
            p = __bfloat1622float2(a3); f3 += p.x + p.y;
        }
        s_red[h][jg      ] = f0;
        s_red[h][jg + 80 ] = f1;
        s_red[h][jg + 160] = f2;
        s_red[h][jg + 240] = f3;
        __syncthreads();

        float o = 0.f;
        if (is_red) {
#pragma unroll
            for (int hh = 0; hh < HSPLIT; ++hh) o += s_red[hh][j];
            o *= e;
        }

        if ((t & 7) == 7) {
            // renormalize + accumulate loglik (telescoped)
            if (is_red) s_outf[j] = o;
            __syncthreads();
            if (tid < 32) {
                float s = 0.f;
#pragma unroll
                for (int k = 0; k < 10; ++k) s += s_outf[tid * 10 + k];
#pragma unroll
                for (int off = 16; off > 0; off >>= 1)
                    s += __shfl_xor_sync(0xffffffffu, s, off);
                if (tid == 0) { ll += logf(s); s_inv = 1.0f / s; }
            }
            __syncthreads();
            if (is_red)
                reinterpret_cast<__nv_bfloat16*>(s_alpha32)[j] =
                    __float2bfloat16(o * s_inv);
        } else {
            if (is_red)
                reinterpret_cast<__nv_bfloat16*>(s_alpha32)[j] = __float2bfloat16(o);
        }
        __syncthreads();
    }

    if (tid == 0) out[b] = ll;   // T_LEN multiple of 8 -> last step normalized; ll complete
}

// ---------------------------------------------------------------------------
extern "C" void kernel_launch(void* const* d_in, const int* in_sizes, int n_in,
                              void* d_out, int out_size) {
    const float* inputs = nullptr;
    const float* A      = nullptr;
    const float* Bm     = nullptr;
    const float* Ivec   = nullptr;
    for (int i = 0; i < n_in; ++i) {
        switch (in_sizes[i]) {
            case NBATCH * T_LEN * E_DIM: inputs = (const float*)d_in[i]; break;
            case S_REAL * S_REAL:        A      = (const float*)d_in[i]; break;
            case S_REAL * E_DIM:         Bm     = (const float*)d_in[i]; break;
            case S_REAL:                 Ivec   = (const float*)d_in[i]; break;
            default: break;
        }
    }
    // positional fallback
    if (!inputs) inputs = (const float*)d_in[0];
    if (!A)      A      = (const float*)d_in[1];
    if (!Bm)     Bm     = (const float*)d_in[2];
    if (!Ivec)   Ivec   = (const float*)d_in[3];
    float* out = (float*)d_out;

    prep_apk_kernel<<<(NIP * SP + 255) / 256, 256>>>(A);

    dim3 ggrid(SP / 64, (NBATCH * T_LEN) / 64);   // (5, 2048)
    emis_gemm_kernel<<<ggrid, 256>>>(inputs, Bm);

    scan_kernel<<<NBATCH, SCAN_THREADS>>>(Ivec, out);
    (void)out_size;
}

// round 3
// speedup vs baseline: 1.6090x; 1.6090x over previous
#include <cuda_runtime.h>
#include <cuda_bf16.h>
#include <stdint.h>

#define S_REAL   308
#define SP       320     // padded state count
#define E_DIM    126
#define T_LEN    4096
#define NBATCH   32
#define NIP      160     // SP/2 (i-pairs)
#define JGROUPS  80
#define HSPLIT   8
#define SCAN_THREADS 640
#define KK_RES   12      // A-quads resident in registers per thread
#define KK_TOT   20

// Scratch (device globals — no allocation in kernel_launch)
__device__ __nv_bfloat16 g_emis[(size_t)NBATCH * T_LEN * SP];   // 80 MB
__device__ uint32_t      g_apk[NIP * SP];                        // packed A, 200 KB

__device__ __forceinline__ __nv_bfloat162 u32_bf2(uint32_t v) {
    return *reinterpret_cast<__nv_bfloat162*>(&v);
}
__device__ __forceinline__ uint32_t bf2_u32(__nv_bfloat162 v) {
    return *reinterpret_cast<uint32_t*>(&v);
}

// ---------------------------------------------------------------------------
// Pack A (fp32 [308][308]) into bf16x2 words.
// Word for (ip, j): lo = A[2ip][j], hi = A[2ip+1][j], zero-padded to 320x320.
// Stored at g_apk[(ip*80 + jg)*4 + q] where j = jg + 80*q, so one LDG.128 per
// thread fetches its 4 strided-j words; a warp (consecutive jg) reads 512B.
// ---------------------------------------------------------------------------
__global__ void prep_apk_kernel(const float* __restrict__ A) {
    int idx = blockIdx.x * blockDim.x + threadIdx.x;
    if (idx >= NIP * SP) return;
    int ip = idx / SP;
    int j  = idx - ip * SP;
    int i0 = 2 * ip, i1 = i0 + 1;
    float a0 = (i0 < S_REAL && j < S_REAL) ? A[i0 * S_REAL + j] : 0.f;
    float a1 = (i1 < S_REAL && j < S_REAL) ? A[i1 * S_REAL + j] : 0.f;
    __nv_bfloat162 w = __floats2bfloat162_rn(a0, a1);  // lo = a0, hi = a1
    int jg = j % JGROUPS, q = j / JGROUPS;
    g_apk[(ip * JGROUPS + jg) * 4 + q] = bf2_u32(w);
}

// ---------------------------------------------------------------------------
// Emission GEMM (bf16x2 / HFMA2): emis[m][n] = sum_e inputs[m][e] * B[n][e]
// M=131072, N=320 (308 real), K=126 (padded to 128). 64x64 tiles, 256 thr,
// 4x4 microtile, bf16x2 accumulation over each 32-k block, fp32 collapse.
// ---------------------------------------------------------------------------
__global__ void __launch_bounds__(256)
emis_gemm_kernel(const float* __restrict__ inp, const float* __restrict__ Bm) {
    __shared__ uint32_t sAp[64][16];   // [m][kp]  bf16x2 over (2kp, 2kp+1)
    __shared__ uint32_t sBp[16][64];   // [kp][n]

    const int tid = threadIdx.x;
    const int tx = tid & 15;       // n microtile
    const int ty = tid >> 4;       // m microtile
    const int n0 = blockIdx.x * 64;
    const int m0 = blockIdx.y * 64;

    float acc[4][4];
#pragma unroll
    for (int u = 0; u < 4; ++u)
#pragma unroll
        for (int v = 0; v < 4; ++v) acc[u][v] = 0.f;

    const __nv_bfloat162 zero2 = __floats2bfloat162_rn(0.f, 0.f);

    for (int k0 = 0; k0 < 128; k0 += 32) {
        // load inputs tile -> bf16x2 pairs: 64 m x 16 kp, 4 words/thread
#pragma unroll
        for (int r = 0; r < 4; ++r) {
            int lin = tid + r * 256;
            int mm = lin >> 4, kp = lin & 15;
            int k = k0 + 2 * kp;
            __nv_bfloat162 w = zero2;
            if (k < E_DIM) {   // pairs never straddle E_DIM (both even)
                float2 f = *reinterpret_cast<const float2*>(
                    &inp[(size_t)(m0 + mm) * E_DIM + k]);
                w = __floats2bfloat162_rn(f.x, f.y);
            }
            sAp[mm][kp] = bf2_u32(w);
        }
        // load B tile -> bf16x2: sBp[kp][n] = (B[n0+n][k], B[n0+n][k+1])
#pragma unroll
        for (int r = 0; r < 4; ++r) {
            int lin = tid + r * 256;
            int kp = lin >> 6, n = lin & 63;
            int k = k0 + 2 * kp;
            int nn = n0 + n;
            __nv_bfloat162 w = zero2;
            if (k < E_DIM && nn < S_REAL) {
                float2 f = *reinterpret_cast<const float2*>(
                    &Bm[(size_t)nn * E_DIM + k]);
                w = __floats2bfloat162_rn(f.x, f.y);
            }
            sBp[kp][n] = bf2_u32(w);
        }
        __syncthreads();

        __nv_bfloat162 acc2[4][4];
#pragma unroll
        for (int u = 0; u < 4; ++u)
#pragma unroll
            for (int v = 0; v < 4; ++v) acc2[u][v] = zero2;

#pragma unroll
        for (int kp = 0; kp < 16; ++kp) {
            uint4 bv = *reinterpret_cast<const uint4*>(&sBp[kp][tx * 4]);
            uint32_t a0 = sAp[ty * 4 + 0][kp];
            uint32_t a1 = sAp[ty * 4 + 1][kp];
            uint32_t a2 = sAp[ty * 4 + 2][kp];
            uint32_t a3 = sAp[ty * 4 + 3][kp];
            __nv_bfloat162 b0 = u32_bf2(bv.x), b1 = u32_bf2(bv.y);
            __nv_bfloat162 b2 = u32_bf2(bv.z), b3 = u32_bf2(bv.w);
            acc2[0][0] = __hfma2(u32_bf2(a0), b0, acc2[0][0]);
            acc2[0][1] = __hfma2(u32_bf2(a0), b1, acc2[0][1]);
            acc2[0][2] = __hfma2(u32_bf2(a0), b2, acc2[0][2]);
            acc2[0][3] = __hfma2(u32_bf2(a0), b3, acc2[0][3]);
            acc2[1][0] = __hfma2(u32_bf2(a1), b0, acc2[1][0]);
            acc2[1][1] = __hfma2(u32_bf2(a1), b1, acc2[1][1]);
            acc2[1][2] = __hfma2(u32_bf2(a1), b2, acc2[1][2]);
            acc2[1][3] = __hfma2(u32_bf2(a1), b3, acc2[1][3]);
            acc2[2][0] = __hfma2(u32_bf2(a2), b0, acc2[2][0]);
            acc2[2][1] = __hfma2(u32_bf2(a2), b1, acc2[2][1]);
            acc2[2][2] = __hfma2(u32_bf2(a2), b2, acc2[2][2]);
            acc2[2][3] = __hfma2(u32_bf2(a2), b3, acc2[2][3]);
            acc2[3][0] = __hfma2(u32_bf2(a3), b0, acc2[3][0]);
            acc2[3][1] = __hfma2(u32_bf2(a3), b1, acc2[3][1]);
            acc2[3][2] = __hfma2(u32_bf2(a3), b2, acc2[3][2]);
            acc2[3][3] = __hfma2(u32_bf2(a3), b3, acc2[3][3]);
        }
#pragma unroll
        for (int u = 0; u < 4; ++u)
#pragma unroll
            for (int v = 0; v < 4; ++v) {
                float2 p = __bfloat1622float2(acc2[u][v]);
                acc[u][v] += p.x + p.y;
            }
        __syncthreads();
    }
    // store bf16 (pairs)
#pragma unroll
    for (int u = 0; u < 4; ++u) {
        int m = m0 + ty * 4 + u;
        size_t base = (size_t)m * SP + n0 + tx * 4;
#pragma unroll
        for (int v = 0; v < 4; v += 2) {
            __nv_bfloat162 p = __floats2bfloat162_rn(acc[u][v], acc[u][v + 1]);
            *reinterpret_cast<uint32_t*>(&g_emis[base + v]) = bf2_u32(p);
        }
    }
}

// ---------------------------------------------------------------------------
// Scan kernel: one CTA per batch, 640 thr = 8 i-splits x 80 j-groups.
// A slice per thread = 20 quads; 12 held in registers for the whole kernel,
// 8 streamed from L1 each step. HFMA2 over bf16x2 i-pairs, single 20-term
// bf16 accumulation collapsed to fp32. Cross-h reduce via smem. Alpha kept
// unnormalized; renormalize + log-accumulate every 8 steps (telescoped).
// ---------------------------------------------------------------------------
__global__ void __launch_bounds__(SCAN_THREADS, 1)
scan_kernel(const float* __restrict__ Ivec, float* __restrict__ out) {
    __shared__ uint32_t s_alpha32[NIP];        // bf16 alpha[320] as pairs
    __shared__ float    s_red[HSPLIT][SP];
    __shared__ float    s_outf[SP];
    __shared__ float    s_inv;

    const int b   = blockIdx.x;
    const int tid = threadIdx.x;
    const int h   = tid / JGROUPS;             // 0..7
    const int jg  = tid - h * JGROUPS;         // 0..79
    const bool is_red = (tid < SP);
    const int j = tid;

    const __nv_bfloat16* erow = g_emis + (size_t)b * T_LEN * SP;
    const uint4* Ap = reinterpret_cast<const uint4*>(g_apk)
                      + (h * KK_TOT) * JGROUPS + jg;

    // resident A quads (48 regs, live for whole kernel)
    uint4 rA[KK_RES];
#pragma unroll
    for (int kk = 0; kk < KK_RES; ++kk) rA[kk] = Ap[kk * JGROUPS];

    float ll = 0.f;

    // t = 0: alpha0 = I * e0 (unnormalized)
    if (is_red) {
        float e0 = __bfloat162float(erow[j]);
        float w  = (j < S_REAL) ? Ivec[j] : 0.f;
        reinterpret_cast<__nv_bfloat16*>(s_alpha32)[j] = __float2bfloat16(w * e0);
    }
    __syncthreads();

    // prefetch emission for t=1
    float e_cur = 0.f;
    if (is_red) e_cur = __bfloat162float(erow[(size_t)SP + j]);

    const __nv_bfloat162 zero2 = __floats2bfloat162_rn(0.f, 0.f);

    for (int t = 1; t < T_LEN; ++t) {
        // prefetch emission for the NEXT step (fully hidden behind compute)
        float e_next = 0.f;
        if (t + 1 < T_LEN && is_red)
            e_next = __bfloat162float(erow[(size_t)(t + 1) * SP + j]);

        // alpha pair-words for this h-slice (broadcast LDS.128)
        uint4 av[5];
        const uint4* al4 = reinterpret_cast<const uint4*>(s_alpha32);
#pragma unroll
        for (int r = 0; r < 5; ++r) av[r] = al4[h * 5 + r];
        const uint32_t* aw = reinterpret_cast<const uint32_t*>(av);

        __nv_bfloat162 a0 = zero2, a1 = zero2, a2 = zero2, a3 = zero2;

        // first half of streamed quads issued early (L1-hit latency hiding)
        uint4 sb[8];
#pragma unroll
        for (int r = 0; r < 4; ++r) sb[r] = Ap[(KK_RES + r) * JGROUPS];

        // resident part: kk 0..11
#pragma unroll
        for (int kk = 0; kk < KK_RES; ++kk) {
            uint4 w = rA[kk];
            __nv_bfloat162 al = u32_bf2(aw[kk]);
            a0 = __hfma2(u32_bf2(w.x), al, a0);
            a1 = __hfma2(u32_bf2(w.y), al, a1);
            a2 = __hfma2(u32_bf2(w.z), al, a2);
            a3 = __hfma2(u32_bf2(w.w), al, a3);
        }

        // second half of streamed quads
#pragma unroll
        for (int r = 4; r < 8; ++r) sb[r] = Ap[(KK_RES + r) * JGROUPS];

        // streamed part: kk 12..19
#pragma unroll
        for (int r = 0; r < 8; ++r) {
            uint4 w = sb[r];
            __nv_bfloat162 al = u32_bf2(aw[KK_RES + r]);
            a0 = __hfma2(u32_bf2(w.x), al, a0);
            a1 = __hfma2(u32_bf2(w.y), al, a1);
            a2 = __hfma2(u32_bf2(w.z), al, a2);
            a3 = __hfma2(u32_bf2(w.w), al, a3);
        }

        float2 p;
        float f0, f1, f2, f3;
        p = __bfloat1622float2(a0); f0 = p.x + p.y;
        p = __bfloat1622float2(a1); f1 = p.x + p.y;
        p = __bfloat1622float2(a2); f2 = p.x + p.y;
        p = __bfloat1622float2(a3); f3 = p.x + p.y;

        s_red[h][jg      ] = f0;
        s_red[h][jg + 80 ] = f1;
        s_red[h][jg + 160] = f2;
        s_red[h][jg + 240] = f3;
        __syncthreads();

        float o = 0.f;
        if (is_red) {
#pragma unroll
            for (int hh = 0; hh < HSPLIT; ++hh) o += s_red[hh][j];
            o *= e_cur;
        }

        if ((t & 7) == 7) {
            // renormalize + accumulate loglik (telescoped)
            if (is_red) s_outf[j] = o;
            __syncthreads();
            if (tid < 32) {
                float s = 0.f;
#pragma unroll
                for (int k = 0; k < 10; ++k) s += s_outf[tid * 10 + k];
#pragma unroll
                for (int off = 16; off > 0; off >>= 1)
                    s += __shfl_xor_sync(0xffffffffu, s, off);
                if (tid == 0) { ll += logf(s); s_inv = 1.0f / s; }
            }
            __syncthreads();
            if (is_red)
                reinterpret_cast<__nv_bfloat16*>(s_alpha32)[j] =
                    __float2bfloat16(o * s_inv);
        } else {
            if (is_red)
                reinterpret_cast<__nv_bfloat16*>(s_alpha32)[j] = __float2bfloat16(o);
        }
        __syncthreads();

        e_cur = e_next;
    }

    if (tid == 0) out[b] = ll;   // T_LEN % 8 == 0 -> ll complete
}

// ---------------------------------------------------------------------------
extern "C" void kernel_launch(void* const* d_in, const int* in_sizes, int n_in,
                              void* d_out, int out_size) {
    const float* inputs = nullptr;
    const float* A      = nullptr;
    const float* Bm     = nullptr;
    const float* Ivec   = nullptr;
    for (int i = 0; i < n_in; ++i) {
        switch (in_sizes[i]) {
            case NBATCH * T_LEN * E_DIM: inputs = (const float*)d_in[i]; break;
            case S_REAL * S_REAL:        A      = (const float*)d_in[i]; break;
            case S_REAL * E_DIM:         Bm     = (const float*)d_in[i]; break;
            case S_REAL:                 Ivec   = (const float*)d_in[i]; break;
            default: break;
        }
    }
    if (!inputs) inputs = (const float*)d_in[0];
    if (!A)      A      = (const float*)d_in[1];
    if (!Bm)     Bm     = (const float*)d_in[2];
    if (!Ivec)   Ivec   = (const float*)d_in[3];
    float* out = (float*)d_out;

    prep_apk_kernel<<<(NIP * SP + 255) / 256, 256>>>(A);

    dim3 ggrid(SP / 64, (NBATCH * T_LEN) / 64);   // (5, 2048)
    emis_gemm_kernel<<<ggrid, 256>>>(inputs, Bm);

    scan_kernel<<<NBATCH, SCAN_THREADS>>>(Ivec, out);
    (void)out_size;
}